// round 15
// baseline (speedup 1.0000x reference)
#include <cuda_runtime.h>
#include <cuda_fp16.h>
#include <math.h>
#include <stdint.h>

#define B_ 2
#define L_ 2048
#define H_ 2048
#define K_ 128
#define BL_ (B_*L_)
#define NT_ (L_/64)
#define SCALE_ 0.08838834764831845f
#define EPS_ 1e-5f

// ---------------- scratch ----------------
__device__ float g_q[BL_*K_];
__device__ float g_k[BL_*K_];
__device__ float g_D[BL_*K_];
__device__ float g_A[B_*NT_*128*64];
__device__ float g_rs[BL_];            // per-row rsqrt(mean(o^2)+eps)
__device__ __half g_O16[BL_*H_];       // o fp16
__device__ __half g_Xh[BL_*H_];        // x hi fp16
__device__ __half g_Xl[BL_*H_];        // x lo fp16
__device__ __half g_Wh[256*H_];        // [Wq;Wk] hi
__device__ __half g_Wl[256*H_];        // [Wq;Wk] lo
__device__ __half g_Bh[H_*2*H_];       // [Wog|Wig] fp16

__device__ __forceinline__ float sigmoid_f(float v) { return 1.f/(1.f+expf(-v)); }

__device__ __forceinline__ uint32_t smem_u32(const void* p) {
    uint32_t a;
    asm("{ .reg .u64 t; cvta.to.shared.u64 t, %1; cvt.u32.u64 %0, t; }" : "=r"(a) : "l"(p));
    return a;
}
#define CP_ASYNC16(dst, src) asm volatile("cp.async.cg.shared.global [%0], [%1], 16;" :: "r"(dst), "l"(src))
#define CP_COMMIT() asm volatile("cp.async.commit_group;" ::: "memory")
#define CP_WAIT(n)  asm volatile("cp.async.wait_group %0;" :: "n"(n) : "memory")

// ============ 0) fused conversions: x hi/lo, W hi/lo, B fp16 ============
#define NBLK_X 8192
#define NBLK_W 512
#define NBLK_B 8192
__global__ void conv_all_kernel(const float* __restrict__ x,
                                const float* __restrict__ Wq,
                                const float* __restrict__ Wk,
                                const float* __restrict__ Wog,
                                const float* __restrict__ Wig) {
    int bid = blockIdx.x;
    if (bid < NBLK_X) {
        int idx4 = bid * 256 + threadIdx.x;
        float4 v = *reinterpret_cast<const float4*>(x + (size_t)idx4 * 4);
        float a[4] = {v.x, v.y, v.z, v.w};
        __half h[4], l[4];
        #pragma unroll
        for (int i = 0; i < 4; ++i) {
            h[i] = __float2half_rn(a[i]);
            l[i] = __float2half_rn(a[i] - __half2float(h[i]));
        }
        size_t o = (size_t)idx4 * 4;
        __half2 p;
        p.x = h[0]; p.y = h[1]; *reinterpret_cast<__half2*>(&g_Xh[o])   = p;
        p.x = h[2]; p.y = h[3]; *reinterpret_cast<__half2*>(&g_Xh[o+2]) = p;
        p.x = l[0]; p.y = l[1]; *reinterpret_cast<__half2*>(&g_Xl[o])   = p;
        p.x = l[2]; p.y = l[3]; *reinterpret_cast<__half2*>(&g_Xl[o+2]) = p;
    } else if (bid < NBLK_X + NBLK_W) {
        int idx4 = (bid - NBLK_X) * 256 + threadIdx.x;
        int row = idx4 >> 9;
        int col = (idx4 & 511) * 4;
        const float* src = (row < 128) ? &Wq[(size_t)row * H_ + col]
                                       : &Wk[(size_t)(row - 128) * H_ + col];
        float4 v = *reinterpret_cast<const float4*>(src);
        float a[4] = {v.x, v.y, v.z, v.w};
        __half h[4], l[4];
        #pragma unroll
        for (int i = 0; i < 4; ++i) {
            h[i] = __float2half_rn(a[i]);
            l[i] = __float2half_rn(a[i] - __half2float(h[i]));
        }
        size_t o = (size_t)row * H_ + col;
        __half2 p;
        p.x = h[0]; p.y = h[1]; *reinterpret_cast<__half2*>(&g_Wh[o])   = p;
        p.x = h[2]; p.y = h[3]; *reinterpret_cast<__half2*>(&g_Wh[o+2]) = p;
        p.x = l[0]; p.y = l[1]; *reinterpret_cast<__half2*>(&g_Wl[o])   = p;
        p.x = l[2]; p.y = l[3]; *reinterpret_cast<__half2*>(&g_Wl[o+2]) = p;
    } else {
        int idx4 = (bid - NBLK_X - NBLK_W) * 256 + threadIdx.x;
        int row = idx4 >> 10;
        int col = (idx4 & 1023) * 4;
        const float* src = (col < H_) ? &Wog[(size_t)row * H_ + col]
                                      : &Wig[(size_t)row * H_ + (col - H_)];
        float4 v = *reinterpret_cast<const float4*>(src);
        __half2 p0, p1;
        p0.x = __float2half_rn(v.x); p0.y = __float2half_rn(v.y);
        p1.x = __float2half_rn(v.z); p1.y = __float2half_rn(v.w);
        size_t o = (size_t)row * (2*H_) + col;
        *reinterpret_cast<__half2*>(&g_Bh[o])   = p0;
        *reinterpret_cast<__half2*>(&g_Bh[o+2]) = p1;
    }
}

// ============ 1) proj via mma: [q|k] = x @ [Wq;Wk]^T  (3-term split) ============
// tile 64m x 64n, BK=64, 3 stages, 128 threads (4 warps, warp tile 16x64)
#define P_ITERS  96
#define P_PITCH  144
#define P_ATILE  (64*P_PITCH)
#define P_STAGE  (128*P_PITCH)   // 18432
#define P_SMEM   (3*P_STAGE)     // 55296

__device__ __forceinline__ void p_load_stage(uint32_t sbase, int stage, int it,
                                             int m0, int n0, int tid) {
    const int term = it >> 5;
    const int kofs = (it & 31) * 64;
    const __half* Ap = (term == 1) ? g_Xl : g_Xh;
    const __half* Bp = (term == 2) ? g_Wl : g_Wh;
    const uint32_t sA = sbase + stage * P_STAGE;
    const uint32_t sB = sA + P_ATILE;
    #pragma unroll
    for (int i = 0; i < 4; ++i) {
        int g = tid + i * 128;
        int r = g >> 3, c = g & 7;
        CP_ASYNC16(sA + r * P_PITCH + c * 16,
                   Ap + (size_t)(m0 + r) * H_ + kofs + c * 8);
    }
    #pragma unroll
    for (int i = 0; i < 4; ++i) {
        int g = tid + i * 128;
        int r = g >> 3, c = g & 7;
        CP_ASYNC16(sB + r * P_PITCH + c * 16,
                   Bp + (size_t)(n0 + r) * H_ + kofs + c * 8);
    }
}

__global__ void __launch_bounds__(128, 4) proj_tc_kernel() {
    extern __shared__ char smem[];
    const uint32_t sbase = smem_u32(smem);
    const int tid = threadIdx.x;
    const int lane = tid & 31;
    const int wm = tid >> 5;        // 4 warps in m (16 rows each)
    const int m0 = blockIdx.y * 64;
    const int n0 = blockIdx.x * 64;

    const uint32_t aAddr = (uint32_t)((wm*16 + (lane & 15)) * P_PITCH + ((lane >> 4) & 1) * 16);
    const uint32_t bAddr = (uint32_t)(P_ATILE +
                    ((lane & 7) + ((lane & 16) ? 8 : 0)) * P_PITCH +
                    ((lane & 8) ? 16 : 0));

    float c[8][4];
    #pragma unroll
    for (int j = 0; j < 8; ++j)
        #pragma unroll
        for (int q = 0; q < 4; ++q) c[j][q] = 0.f;

    p_load_stage(sbase, 0, 0, m0, n0, tid); CP_COMMIT();
    p_load_stage(sbase, 1, 1, m0, n0, tid); CP_COMMIT();

    int stage = 0;
    #pragma unroll 1
    for (int it = 0; it < P_ITERS; ++it) {
        CP_WAIT(1);
        __syncthreads();
        if (it + 2 < P_ITERS) {
            int ns = stage + 2; if (ns >= 3) ns -= 3;
            p_load_stage(sbase, ns, it + 2, m0, n0, tid);
        }
        CP_COMMIT();

        const uint32_t stoff = sbase + stage * P_STAGE;
        #pragma unroll
        for (int ks = 0; ks < 4; ++ks) {
            uint32_t af[4];
            asm volatile("ldmatrix.sync.aligned.m8n8.x4.shared.b16 {%0,%1,%2,%3}, [%4];"
                : "=r"(af[0]), "=r"(af[1]), "=r"(af[2]), "=r"(af[3])
                : "r"(stoff + aAddr + ks * 32));
            uint32_t bf[8][2];
            #pragma unroll
            for (int p = 0; p < 4; ++p) {
                asm volatile("ldmatrix.sync.aligned.m8n8.x4.shared.b16 {%0,%1,%2,%3}, [%4];"
                    : "=r"(bf[p*2][0]), "=r"(bf[p*2][1]), "=r"(bf[p*2+1][0]), "=r"(bf[p*2+1][1])
                    : "r"(stoff + bAddr + p * (16*P_PITCH) + ks * 32));
            }
            #pragma unroll
            for (int ni = 0; ni < 8; ++ni) {
                asm volatile(
                    "mma.sync.aligned.m16n8k16.row.col.f32.f16.f16.f32 "
                    "{%0,%1,%2,%3}, {%4,%5,%6,%7}, {%8,%9}, {%0,%1,%2,%3};"
                    : "+f"(c[ni][0]), "+f"(c[ni][1]),
                      "+f"(c[ni][2]), "+f"(c[ni][3])
                    : "r"(af[0]), "r"(af[1]), "r"(af[2]), "r"(af[3]),
                      "r"(bf[ni][0]), "r"(bf[ni][1]));
            }
        }
        if (++stage == 3) stage = 0;
    }

    const int gid = lane >> 2, tig = lane & 3;
    #pragma unroll
    for (int ni = 0; ni < 8; ++ni) {
        #pragma unroll
        for (int q = 0; q < 4; ++q) {
            int row = m0 + wm*16 + gid + (q >> 1) * 8;
            int cg  = n0 + ni*8 + tig*2 + (q & 1);
            float v = c[ni][q];
            if (cg < 128) {
                g_q[row*K_ + cg] = v * sigmoid_f(v) * SCALE_;
            } else {
                int col = cg - 128;
                float ks = sigmoid_f(v);
                g_k[row*K_ + col] = ks;
                g_D[row*K_ + col] = 1.f / (1.f + expf(ks));
            }
        }
    }
}

// ============ 2) banded score matrix A[t,s] — one CTA per 16-row sub-block ============
__global__ void __launch_bounds__(512) gla_A_kernel() {
    const int tt = blockIdx.x, b = blockIdx.y, sub = blockIdx.z;
    const int T0 = tt * 64;
    const int Ti = T0 + sub * 16;
    const int base = b * L_;
    const int tid = threadIdx.x;

    __shared__ float skT[128][80];
    __shared__ float sqT[128][16];

    float* At = &g_A[(size_t)(b * NT_ + tt) * 128 * 64];
    for (int idx = tid; idx < 128 * 16; idx += 512) {
        int r = idx >> 4, c = idx & 15;
        At[r * 64 + sub * 16 + c] = 0.f;
    }

    for (int idx = tid; idx < 79 * 128; idx += 512) {
        int si = idx >> 7;
        int k  = idx & 127;
        int s  = Ti - 63 + si;
        skT[k][si] = (s >= 0) ? g_k[(base + s) * K_ + k] : 0.f;
    }
    __syncthreads();
    if (tid < 128) {
        int k = tid;
        float p = 1.f;
        for (int si = 62; si >= 0; --si) {
            int u = Ti - 62 + si;
            float d = (u >= 0) ? g_D[(base + u) * K_ + k] : 1.f;
            p *= d;
            skT[k][si] *= p;
        }
    } else if (tid < 256) {
        int k = tid - 128;
        sqT[k][0] = g_q[(base + Ti) * K_ + k];
        float ap = 1.f;
        #pragma unroll
        for (int j = 1; j < 16; ++j) {
            int u = Ti + j;
            ap *= g_D[(base + u) * K_ + k];
            sqT[k][j] = g_q[(base + u) * K_ + k] * ap;
            skT[k][63 + j] *= (1.f / ap);
        }
    }
    __syncthreads();
    for (int r = 0; r < 3; ++r) {
        int p  = r * 512 + tid;
        int ti = p / 80;
        int si = p - ti * 80;
        if (ti < 16 && si < 79 && si >= ti && si <= ti + 63) {
            float acc = 0.f;
            #pragma unroll 16
            for (int k = 0; k < 128; ++k)
                acc += sqT[k][ti] * skT[k][si];
            int sidx = sub * 16 + 1 + si;
            At[sidx * 64 + sub * 16 + ti] = acc;
        }
    }
}

// ============ 3) o = A_band @ X via mma (A exact split, X hi only) ============
#define OV_PITCH 272
#define O_AMAT   (64*OV_PITCH)
#define O_XMAT   (128*OV_PITCH)
#define O_XBASE  (2*O_AMAT)
#define O_SMEM   (O_XBASE + 2*O_XMAT)   // 104448

__global__ void __launch_bounds__(256, 2) gla_o_tc_kernel() {
    extern __shared__ char smem[];
    const uint32_t sb = smem_u32(smem);
    const int vt = blockIdx.x, tt = blockIdx.y, b = blockIdx.z;
    const int T0 = tt * 64;
    const int tid = threadIdx.x;
    const int lane = tid & 31, wid = tid >> 5;
    const int wm = wid & 1, wn = wid >> 1;

    const float* At = &g_A[(size_t)(b * NT_ + tt) * 128 * 64];
    #pragma unroll
    for (int i = 0; i < 32; ++i) {
        int idx = tid + i * 256;
        float v = At[idx];
        int t = idx & 63, sidx = idx >> 6;
        __half h = __float2half_rn(v);
        __half l = __float2half_rn(v - __half2float(h));
        *reinterpret_cast<__half*>(smem + t * OV_PITCH + sidx * 2) = h;
        *reinterpret_cast<__half*>(smem + O_AMAT + t * OV_PITCH + sidx * 2) = l;
    }

    #pragma unroll
    for (int vc = 0; vc < 2; ++vc) {
        const int v0 = vt * 256 + vc * 128;
        const uint32_t sX = sb + O_XBASE + vc * O_XMAT;
        #pragma unroll
        for (int i = 0; i < 8; ++i) {
            int g = tid + i * 256;
            int r = g >> 4, cc = g & 15;
            int srow = T0 - 64 + r;
            size_t grow = (size_t)(b * L_ + (srow < 0 ? 0 : srow)) * H_ + v0 + cc * 8;
            CP_ASYNC16(sX + r * OV_PITCH + cc * 16, g_Xh + grow);
        }
        CP_COMMIT();
    }

    const uint32_t aAddr = sb + (uint32_t)((wm*32 + (lane & 15)) * OV_PITCH + ((lane >> 4) & 1) * 16);
    const int gid = lane >> 2, tig = lane & 3;

    #pragma unroll
    for (int vc = 0; vc < 2; ++vc) {
        if (vc == 0) { CP_WAIT(1); } else { CP_WAIT(0); }
        __syncthreads();

        const uint32_t sX = sb + O_XBASE + vc * O_XMAT;
        const uint32_t bAddr = sX + (uint32_t)((lane & 15) * OV_PITCH + (wn*32) * 2);

        float acc[2][4][4];
        #pragma unroll
        for (int i = 0; i < 2; ++i)
            #pragma unroll
            for (int j = 0; j < 4; ++j)
                #pragma unroll
                for (int q = 0; q < 4; ++q) acc[i][j][q] = 0.f;

        #pragma unroll
        for (int ks = 0; ks < 8; ++ks) {
            uint32_t ah[2][4], al[2][4];
            #pragma unroll
            for (int mi = 0; mi < 2; ++mi) {
                asm volatile("ldmatrix.sync.aligned.m8n8.x4.shared.b16 {%0,%1,%2,%3}, [%4];"
                    : "=r"(ah[mi][0]), "=r"(ah[mi][1]), "=r"(ah[mi][2]), "=r"(ah[mi][3])
                    : "r"(aAddr + mi * (16*OV_PITCH) + ks * 32));
                asm volatile("ldmatrix.sync.aligned.m8n8.x4.shared.b16 {%0,%1,%2,%3}, [%4];"
                    : "=r"(al[mi][0]), "=r"(al[mi][1]), "=r"(al[mi][2]), "=r"(al[mi][3])
                    : "r"(aAddr + O_AMAT + mi * (16*OV_PITCH) + ks * 32));
            }
            uint32_t bh[4][2];
            #pragma unroll
            for (int nf = 0; nf < 4; ++nf) {
                asm volatile("ldmatrix.sync.aligned.m8n8.x2.trans.shared.b16 {%0,%1}, [%2];"
                    : "=r"(bh[nf][0]), "=r"(bh[nf][1])
                    : "r"(bAddr + ks * (16*OV_PITCH) + nf * 16));
            }
            #pragma unroll
            for (int mi = 0; mi < 2; ++mi)
                #pragma unroll
                for (int nf = 0; nf < 4; ++nf) {
                    asm volatile(
                        "mma.sync.aligned.m16n8k16.row.col.f32.f16.f16.f32 "
                        "{%0,%1,%2,%3}, {%4,%5,%6,%7}, {%8,%9}, {%0,%1,%2,%3};"
                        : "+f"(acc[mi][nf][0]), "+f"(acc[mi][nf][1]),
                          "+f"(acc[mi][nf][2]), "+f"(acc[mi][nf][3])
                        : "r"(ah[mi][0]), "r"(ah[mi][1]), "r"(ah[mi][2]), "r"(ah[mi][3]),
                          "r"(bh[nf][0]), "r"(bh[nf][1]));
                    asm volatile(
                        "mma.sync.aligned.m16n8k16.row.col.f32.f16.f16.f32 "
                        "{%0,%1,%2,%3}, {%4,%5,%6,%7}, {%8,%9}, {%0,%1,%2,%3};"
                        : "+f"(acc[mi][nf][0]), "+f"(acc[mi][nf][1]),
                          "+f"(acc[mi][nf][2]), "+f"(acc[mi][nf][3])
                        : "r"(al[mi][0]), "r"(al[mi][1]), "r"(al[mi][2]), "r"(al[mi][3]),
                          "r"(bh[nf][0]), "r"(bh[nf][1]));
                }
        }

        #pragma unroll
        for (int mi = 0; mi < 2; ++mi) {
            #pragma unroll
            for (int nf = 0; nf < 4; ++nf) {
                int row = T0 + wm*32 + mi*16 + gid;
                int col = vt*256 + vc*128 + wn*32 + nf*8 + tig*2;
                size_t i0 = (size_t)(b * L_ + row) * H_ + col;
                size_t i1 = i0 + 8 * H_;
                __half2 h0; h0.x = __float2half_rn(acc[mi][nf][0]); h0.y = __float2half_rn(acc[mi][nf][1]);
                __half2 h1; h1.x = __float2half_rn(acc[mi][nf][2]); h1.y = __float2half_rn(acc[mi][nf][3]);
                *reinterpret_cast<__half2*>(&g_O16[i0]) = h0;
                *reinterpret_cast<__half2*>(&g_O16[i1]) = h1;
            }
        }
    }
}

// ============ 3b) per-row rms factor from o16 ============
__global__ void rms_kernel() {
    const int m = blockIdx.x;
    const int tid = threadIdx.x;
    const __half* orow = &g_O16[(size_t)m * H_];
    float ss = 0.f;
    #pragma unroll
    for (int t = 0; t < 4; ++t) {
        __half2 h = *reinterpret_cast<const __half2*>(&orow[tid * 8 + t * 2]);
        float2 f = __half22float2(h);
        ss += f.x * f.x + f.y * f.y;
    }
    #pragma unroll
    for (int o = 16; o > 0; o >>= 1)
        ss += __shfl_xor_sync(0xffffffffu, ss, o);
    __shared__ float red[8];
    if ((tid & 31) == 0) red[tid >> 5] = ss;
    __syncthreads();
    if (tid == 0) {
        float t = 0.f;
        #pragma unroll
        for (int i = 0; i < 8; ++i) t += red[i];
        g_rs[m] = rsqrtf(t * (1.f / H_) + EPS_);
    }
}

// ============ 4) mma GEMM 128x128 tiles, 8 warps (64x32 each), occ 2 ============
#define G_ITERS  64
#define G_PITCH  144
#define G_ATILE  (128*G_PITCH)
#define G_STAGE  (256*G_PITCH)   // 36864
#define G_SMEM   (3*G_STAGE)     // 110592

__device__ __forceinline__ void g_load_stage(uint32_t sbase, int stage, int it,
                                             int m0, int n0, int tid) {
    const int kofs = it * 64;
    const __half* Ap = (kofs < H_) ? (g_O16 + kofs) : (g_Xh + (kofs - H_));
    const uint32_t sA = sbase + stage * G_STAGE;
    const uint32_t sB = sA + G_ATILE;
    #pragma unroll
    for (int i = 0; i < 4; ++i) {
        int g = tid + i * 256;
        int r = g >> 3, c = g & 7;
        CP_ASYNC16(sA + r * G_PITCH + c * 16,
                   Ap + (size_t)(m0 + r) * H_ + c * 8);
    }
    #pragma unroll
    for (int i = 0; i < 4; ++i) {
        int g = tid + i * 256;
        int r = g >> 3, c = g & 7;
        CP_ASYNC16(sB + r * G_PITCH + c * 16,
                   g_Bh + (size_t)(n0 + r) * (2*H_) + kofs + c * 8);
    }
}

__global__ void __launch_bounds__(256, 2) gemm_tc_kernel(const float* __restrict__ gw,
                                                         float* __restrict__ out) {
    extern __shared__ char smem[];
    const uint32_t sbase = smem_u32(smem);
    const int tid = threadIdx.x;
    const int lane = tid & 31;
    const int wid = tid >> 5;
    const int wm = wid & 1;          // 2 warps in m (64 rows each)
    const int wn = wid >> 1;         // 4 warps in n (32 cols each)
    const int m0 = blockIdx.y * 128;
    const int n0 = blockIdx.x * 128;

    const uint32_t aAddr = (uint32_t)((wm*64 + (lane & 15)) * G_PITCH + ((lane >> 4) & 1) * 16);
    const uint32_t bAddr = (uint32_t)(G_ATILE +
                    (wn*32 + (lane & 7) + ((lane & 16) ? 8 : 0)) * G_PITCH +
                    ((lane & 8) ? 16 : 0));

    float c[4][4][4];
    #pragma unroll
    for (int i = 0; i < 4; ++i)
        #pragma unroll
        for (int j = 0; j < 4; ++j)
            #pragma unroll
            for (int q = 0; q < 4; ++q) c[i][j][q] = 0.f;

    g_load_stage(sbase, 0, 0, m0, n0, tid); CP_COMMIT();
    g_load_stage(sbase, 1, 1, m0, n0, tid); CP_COMMIT();

    int stage = 0;
    #pragma unroll 1
    for (int it = 0; it < G_ITERS; ++it) {
        CP_WAIT(1);
        __syncthreads();
        if (it + 2 < G_ITERS) {
            int ns = stage + 2; if (ns >= 3) ns -= 3;
            g_load_stage(sbase, ns, it + 2, m0, n0, tid);
        }
        CP_COMMIT();

        const uint32_t stoff = sbase + stage * G_STAGE;
        #pragma unroll
        for (int ks = 0; ks < 4; ++ks) {
            uint32_t af[4][4];
            #pragma unroll
            for (int mi = 0; mi < 4; ++mi) {
                asm volatile("ldmatrix.sync.aligned.m8n8.x4.shared.b16 {%0,%1,%2,%3}, [%4];"
                    : "=r"(af[mi][0]), "=r"(af[mi][1]), "=r"(af[mi][2]), "=r"(af[mi][3])
                    : "r"(stoff + aAddr + mi * (16*G_PITCH) + ks * 32));
            }
            uint32_t bf[4][2];
            #pragma unroll
            for (int p = 0; p < 2; ++p) {
                asm volatile("ldmatrix.sync.aligned.m8n8.x4.shared.b16 {%0,%1,%2,%3}, [%4];"
                    : "=r"(bf[p*2][0]), "=r"(bf[p*2][1]), "=r"(bf[p*2+1][0]), "=r"(bf[p*2+1][1])
                    : "r"(stoff + bAddr + p * (16*G_PITCH) + ks * 32));
            }
            #pragma unroll
            for (int mi = 0; mi < 4; ++mi)
                #pragma unroll
                for (int ni = 0; ni < 4; ++ni) {
                    asm volatile(
                        "mma.sync.aligned.m16n8k16.row.col.f32.f16.f16.f32 "
                        "{%0,%1,%2,%3}, {%4,%5,%6,%7}, {%8,%9}, {%0,%1,%2,%3};"
                        : "+f"(c[mi][ni][0]), "+f"(c[mi][ni][1]),
                          "+f"(c[mi][ni][2]), "+f"(c[mi][ni][3])
                        : "r"(af[mi][0]), "r"(af[mi][1]), "r"(af[mi][2]), "r"(af[mi][3]),
                          "r"(bf[ni][0]), "r"(bf[ni][1]));
                }
        }
        if (++stage == 3) stage = 0;
    }

    // fused epilogue: out = o*rs*gw * go * sigmoid(go)
    const int gid = lane >> 2, tig = lane & 3;
    #pragma unroll
    for (int mi = 0; mi < 4; ++mi) {
        int row = m0 + wm*64 + mi*16 + gid;
        float rs0 = g_rs[row];
        float rs1 = g_rs[row + 8];
        #pragma unroll
        for (int ni = 0; ni < 4; ++ni) {
            int col = n0 + wn*32 + ni*8 + tig*2;
            float2 gwv = *reinterpret_cast<const float2*>(&gw[col]);
            size_t i0 = (size_t)row * H_ + col;
            size_t i1 = i0 + 8 * H_;
            float2 o0 = __half22float2(*reinterpret_cast<const __half2*>(&g_O16[i0]));
            float2 o1 = __half22float2(*reinterpret_cast<const __half2*>(&g_O16[i1]));
            float go;
            float2 r0, r1;
            go = c[mi][ni][0]; r0.x = o0.x * rs0 * gwv.x * go * sigmoid_f(go);
            go = c[mi][ni][1]; r0.y = o0.y * rs0 * gwv.y * go * sigmoid_f(go);
            go = c[mi][ni][2]; r1.x = o1.x * rs1 * gwv.x * go * sigmoid_f(go);
            go = c[mi][ni][3]; r1.y = o1.y * rs1 * gwv.y * go * sigmoid_f(go);
            *reinterpret_cast<float2*>(&out[i0]) = r0;
            *reinterpret_cast<float2*>(&out[i1]) = r1;
        }
    }
}

// ---------------------------------------------------------------------
extern "C" void kernel_launch(void* const* d_in, const int* in_sizes, int n_in,
                              void* d_out, int out_size) {
    const float* x   = (const float*)d_in[0];
    const float* Wq  = (const float*)d_in[1];
    const float* Wk  = (const float*)d_in[2];
    const float* Wog = (const float*)d_in[3];
    const float* Wig = (const float*)d_in[4];
    const float* gw  = (const float*)d_in[5];
    float* out = (float*)d_out;

    cudaFuncSetAttribute(proj_tc_kernel, cudaFuncAttributeMaxDynamicSharedMemorySize, P_SMEM);
    cudaFuncSetAttribute(gla_o_tc_kernel, cudaFuncAttributeMaxDynamicSharedMemorySize, O_SMEM);
    cudaFuncSetAttribute(gemm_tc_kernel, cudaFuncAttributeMaxDynamicSharedMemorySize, G_SMEM);

    conv_all_kernel<<<NBLK_X + NBLK_W + NBLK_B, 256>>>(x, Wq, Wk, Wog, Wig);
    proj_tc_kernel<<<dim3(4, 64),    128, P_SMEM>>>();
    gla_A_kernel <<<dim3(NT_, B_, 4), 512>>>();
    gla_o_tc_kernel<<<dim3(H_/256, NT_, B_), 256, O_SMEM>>>();
    rms_kernel   <<<BL_,             256>>>();
    gemm_tc_kernel<<<dim3(H_/128, BL_/128), 256, G_SMEM>>>(gw, out);
}

// round 17
// speedup vs baseline: 1.4596x; 1.4596x over previous
#include <cuda_runtime.h>
#include <cuda_fp16.h>
#include <math.h>
#include <stdint.h>

#define B_ 2
#define L_ 2048
#define H_ 2048
#define K_ 128
#define BL_ (B_*L_)
#define NT_ (L_/64)
#define SCALE_ 0.08838834764831845f
#define EPS_ 1e-5f

// ---------------- scratch ----------------
__device__ float g_q[BL_*K_];
__device__ float g_k[BL_*K_];
__device__ float g_D[BL_*K_];
__device__ float g_A[B_*NT_*128*64];
__device__ float g_rs[BL_];            // per-row rsqrt(mean(o^2)+eps)
__device__ __half g_O16[BL_*H_];       // o fp16
__device__ __half g_Xh[BL_*H_];        // x hi fp16
__device__ __half g_Xl[BL_*H_];        // x lo fp16
__device__ __half g_Wh[256*H_];        // [Wq;Wk] hi
__device__ __half g_Wl[256*H_];        // [Wq;Wk] lo
__device__ __half g_Bh[H_*2*H_];       // [Wog|Wig] fp16

__device__ __forceinline__ float sigmoid_f(float v) { return 1.f/(1.f+expf(-v)); }

__device__ __forceinline__ uint32_t smem_u32(const void* p) {
    uint32_t a;
    asm("{ .reg .u64 t; cvta.to.shared.u64 t, %1; cvt.u32.u64 %0, t; }" : "=r"(a) : "l"(p));
    return a;
}
#define CP_ASYNC16(dst, src) asm volatile("cp.async.cg.shared.global [%0], [%1], 16;" :: "r"(dst), "l"(src))
#define CP_COMMIT() asm volatile("cp.async.commit_group;" ::: "memory")
#define CP_WAIT(n)  asm volatile("cp.async.wait_group %0;" :: "n"(n) : "memory")

// ============ 0) fused conversions: x hi/lo, W hi/lo, B fp16 ============
#define NBLK_X 8192
#define NBLK_W 512
#define NBLK_B 8192
__global__ void conv_all_kernel(const float* __restrict__ x,
                                const float* __restrict__ Wq,
                                const float* __restrict__ Wk,
                                const float* __restrict__ Wog,
                                const float* __restrict__ Wig) {
    int bid = blockIdx.x;
    if (bid < NBLK_X) {
        int idx4 = bid * 256 + threadIdx.x;
        float4 v = *reinterpret_cast<const float4*>(x + (size_t)idx4 * 4);
        float a[4] = {v.x, v.y, v.z, v.w};
        __half h[4], l[4];
        #pragma unroll
        for (int i = 0; i < 4; ++i) {
            h[i] = __float2half_rn(a[i]);
            l[i] = __float2half_rn(a[i] - __half2float(h[i]));
        }
        size_t o = (size_t)idx4 * 4;
        __half2 p;
        p.x = h[0]; p.y = h[1]; *reinterpret_cast<__half2*>(&g_Xh[o])   = p;
        p.x = h[2]; p.y = h[3]; *reinterpret_cast<__half2*>(&g_Xh[o+2]) = p;
        p.x = l[0]; p.y = l[1]; *reinterpret_cast<__half2*>(&g_Xl[o])   = p;
        p.x = l[2]; p.y = l[3]; *reinterpret_cast<__half2*>(&g_Xl[o+2]) = p;
    } else if (bid < NBLK_X + NBLK_W) {
        int idx4 = (bid - NBLK_X) * 256 + threadIdx.x;
        int row = idx4 >> 9;
        int col = (idx4 & 511) * 4;
        const float* src = (row < 128) ? &Wq[(size_t)row * H_ + col]
                                       : &Wk[(size_t)(row - 128) * H_ + col];
        float4 v = *reinterpret_cast<const float4*>(src);
        float a[4] = {v.x, v.y, v.z, v.w};
        __half h[4], l[4];
        #pragma unroll
        for (int i = 0; i < 4; ++i) {
            h[i] = __float2half_rn(a[i]);
            l[i] = __float2half_rn(a[i] - __half2float(h[i]));
        }
        size_t o = (size_t)row * H_ + col;
        __half2 p;
        p.x = h[0]; p.y = h[1]; *reinterpret_cast<__half2*>(&g_Wh[o])   = p;
        p.x = h[2]; p.y = h[3]; *reinterpret_cast<__half2*>(&g_Wh[o+2]) = p;
        p.x = l[0]; p.y = l[1]; *reinterpret_cast<__half2*>(&g_Wl[o])   = p;
        p.x = l[2]; p.y = l[3]; *reinterpret_cast<__half2*>(&g_Wl[o+2]) = p;
    } else {
        int idx4 = (bid - NBLK_X - NBLK_W) * 256 + threadIdx.x;
        int row = idx4 >> 10;
        int col = (idx4 & 1023) * 4;
        const float* src = (col < H_) ? &Wog[(size_t)row * H_ + col]
                                      : &Wig[(size_t)row * H_ + (col - H_)];
        float4 v = *reinterpret_cast<const float4*>(src);
        __half2 p0, p1;
        p0.x = __float2half_rn(v.x); p0.y = __float2half_rn(v.y);
        p1.x = __float2half_rn(v.z); p1.y = __float2half_rn(v.w);
        size_t o = (size_t)row * (2*H_) + col;
        *reinterpret_cast<__half2*>(&g_Bh[o])   = p0;
        *reinterpret_cast<__half2*>(&g_Bh[o+2]) = p1;
    }
}

// ============ 1) proj via mma: [q|k] = x @ [Wq;Wk]^T  (3-term split) ============
// tile 128m x 64n, BK=64, 3 stages, 128 threads (4 warps, warp tile 32x64)
#define P_ITERS  96
#define P_PITCH  144
#define P_ATILE  (128*P_PITCH)
#define P_STAGE  (192*P_PITCH)
#define P_SMEM   (3*P_STAGE)

__device__ __forceinline__ void p_load_stage(uint32_t sbase, int stage, int it,
                                             int m0, int n0, int tid) {
    const int term = it >> 5;
    const int kofs = (it & 31) * 64;
    const __half* Ap = (term == 1) ? g_Xl : g_Xh;
    const __half* Bp = (term == 2) ? g_Wl : g_Wh;
    const uint32_t sA = sbase + stage * P_STAGE;
    const uint32_t sB = sA + P_ATILE;
    #pragma unroll
    for (int i = 0; i < 8; ++i) {
        int g = tid + i * 128;
        int r = g >> 3, c = g & 7;
        CP_ASYNC16(sA + r * P_PITCH + c * 16,
                   Ap + (size_t)(m0 + r) * H_ + kofs + c * 8);
    }
    #pragma unroll
    for (int i = 0; i < 4; ++i) {
        int g = tid + i * 128;
        int r = g >> 3, c = g & 7;
        CP_ASYNC16(sB + r * P_PITCH + c * 16,
                   Bp + (size_t)(n0 + r) * H_ + kofs + c * 8);
    }
}

__global__ void __launch_bounds__(128, 2) proj_tc_kernel() {
    extern __shared__ char smem[];
    const uint32_t sbase = smem_u32(smem);
    const int tid = threadIdx.x;
    const int lane = tid & 31;
    const int wm = tid >> 5;
    const int m0 = blockIdx.y * 128;
    const int n0 = blockIdx.x * 64;

    const uint32_t aAddr = (uint32_t)((wm*32 + (lane & 15)) * P_PITCH + ((lane >> 4) & 1) * 16);
    const uint32_t bAddr = (uint32_t)(P_ATILE +
                    ((lane & 7) + ((lane & 16) ? 8 : 0)) * P_PITCH +
                    ((lane & 8) ? 16 : 0));

    float c[2][8][4];
    #pragma unroll
    for (int i = 0; i < 2; ++i)
        #pragma unroll
        for (int j = 0; j < 8; ++j)
            #pragma unroll
            for (int q = 0; q < 4; ++q) c[i][j][q] = 0.f;

    p_load_stage(sbase, 0, 0, m0, n0, tid); CP_COMMIT();
    p_load_stage(sbase, 1, 1, m0, n0, tid); CP_COMMIT();

    int stage = 0;
    #pragma unroll 1
    for (int it = 0; it < P_ITERS; ++it) {
        CP_WAIT(1);
        __syncthreads();
        if (it + 2 < P_ITERS) {
            int ns = stage + 2; if (ns >= 3) ns -= 3;
            p_load_stage(sbase, ns, it + 2, m0, n0, tid);
        }
        CP_COMMIT();

        const uint32_t stoff = sbase + stage * P_STAGE;
        #pragma unroll
        for (int ks = 0; ks < 4; ++ks) {
            uint32_t af[2][4];
            #pragma unroll
            for (int mi = 0; mi < 2; ++mi) {
                asm volatile("ldmatrix.sync.aligned.m8n8.x4.shared.b16 {%0,%1,%2,%3}, [%4];"
                    : "=r"(af[mi][0]), "=r"(af[mi][1]), "=r"(af[mi][2]), "=r"(af[mi][3])
                    : "r"(stoff + aAddr + mi * (16*P_PITCH) + ks * 32));
            }
            uint32_t bf[8][2];
            #pragma unroll
            for (int p = 0; p < 4; ++p) {
                asm volatile("ldmatrix.sync.aligned.m8n8.x4.shared.b16 {%0,%1,%2,%3}, [%4];"
                    : "=r"(bf[p*2][0]), "=r"(bf[p*2][1]), "=r"(bf[p*2+1][0]), "=r"(bf[p*2+1][1])
                    : "r"(stoff + bAddr + p * (16*P_PITCH) + ks * 32));
            }
            #pragma unroll
            for (int mi = 0; mi < 2; ++mi)
                #pragma unroll
                for (int ni = 0; ni < 8; ++ni) {
                    asm volatile(
                        "mma.sync.aligned.m16n8k16.row.col.f32.f16.f16.f32 "
                        "{%0,%1,%2,%3}, {%4,%5,%6,%7}, {%8,%9}, {%0,%1,%2,%3};"
                        : "+f"(c[mi][ni][0]), "+f"(c[mi][ni][1]),
                          "+f"(c[mi][ni][2]), "+f"(c[mi][ni][3])
                        : "r"(af[mi][0]), "r"(af[mi][1]), "r"(af[mi][2]), "r"(af[mi][3]),
                          "r"(bf[ni][0]), "r"(bf[ni][1]));
                }
        }
        if (++stage == 3) stage = 0;
    }

    const int gid = lane >> 2, tig = lane & 3;
    #pragma unroll
    for (int mi = 0; mi < 2; ++mi) {
        #pragma unroll
        for (int ni = 0; ni < 8; ++ni) {
            #pragma unroll
            for (int q = 0; q < 4; ++q) {
                int row = m0 + wm*32 + mi*16 + gid + (q >> 1) * 8;
                int cg  = n0 + ni*8 + tig*2 + (q & 1);
                float v = c[mi][ni][q];
                if (cg < 128) {
                    g_q[row*K_ + cg] = v * sigmoid_f(v) * SCALE_;
                } else {
                    int col = cg - 128;
                    float ks = sigmoid_f(v);
                    g_k[row*K_ + col] = ks;
                    g_D[row*K_ + col] = 1.f / (1.f + expf(ks));
                }
            }
        }
    }
}

// ============ 2) banded score matrix A[t,s] — one CTA per 16-row sub-block ============
__global__ void __launch_bounds__(512) gla_A_kernel() {
    const int tt = blockIdx.x, b = blockIdx.y, sub = blockIdx.z;
    const int T0 = tt * 64;
    const int Ti = T0 + sub * 16;
    const int base = b * L_;
    const int tid = threadIdx.x;

    __shared__ float skT[128][80];
    __shared__ float sqT[128][16];

    float* At = &g_A[(size_t)(b * NT_ + tt) * 128 * 64];
    for (int idx = tid; idx < 128 * 16; idx += 512) {
        int r = idx >> 4, c = idx & 15;
        At[r * 64 + sub * 16 + c] = 0.f;
    }

    for (int idx = tid; idx < 79 * 128; idx += 512) {
        int si = idx >> 7;
        int k  = idx & 127;
        int s  = Ti - 63 + si;
        skT[k][si] = (s >= 0) ? g_k[(base + s) * K_ + k] : 0.f;
    }
    __syncthreads();
    if (tid < 128) {
        int k = tid;
        float p = 1.f;
        for (int si = 62; si >= 0; --si) {
            int u = Ti - 62 + si;
            float d = (u >= 0) ? g_D[(base + u) * K_ + k] : 1.f;
            p *= d;
            skT[k][si] *= p;
        }
    } else if (tid < 256) {
        int k = tid - 128;
        sqT[k][0] = g_q[(base + Ti) * K_ + k];
        float ap = 1.f;
        #pragma unroll
        for (int j = 1; j < 16; ++j) {
            int u = Ti + j;
            ap *= g_D[(base + u) * K_ + k];
            sqT[k][j] = g_q[(base + u) * K_ + k] * ap;
            skT[k][63 + j] *= (1.f / ap);
        }
    }
    __syncthreads();
    for (int r = 0; r < 3; ++r) {
        int p  = r * 512 + tid;
        int ti = p / 80;
        int si = p - ti * 80;
        if (ti < 16 && si < 79 && si >= ti && si <= ti + 63) {
            float acc = 0.f;
            #pragma unroll 16
            for (int k = 0; k < 128; ++k)
                acc += sqT[k][ti] * skT[k][si];
            int sidx = sub * 16 + 1 + si;
            At[sidx * 64 + sub * 16 + ti] = acc;
        }
    }
}

// ============ 3) o = A_band @ X via mma (A exact split, X hi only) ============
#define OV_PITCH 272
#define O_AMAT   (64*OV_PITCH)
#define O_XMAT   (128*OV_PITCH)
#define O_XBASE  (2*O_AMAT)
#define O_SMEM   (O_XBASE + 2*O_XMAT)   // 104448

__global__ void __launch_bounds__(256, 2) gla_o_tc_kernel() {
    extern __shared__ char smem[];
    const uint32_t sb = smem_u32(smem);
    const int vt = blockIdx.x, tt = blockIdx.y, b = blockIdx.z;
    const int T0 = tt * 64;
    const int tid = threadIdx.x;
    const int lane = tid & 31, wid = tid >> 5;
    const int wm = wid & 1, wn = wid >> 1;

    const float* At = &g_A[(size_t)(b * NT_ + tt) * 128 * 64];
    #pragma unroll
    for (int i = 0; i < 32; ++i) {
        int idx = tid + i * 256;
        float v = At[idx];
        int t = idx & 63, sidx = idx >> 6;
        __half h = __float2half_rn(v);
        __half l = __float2half_rn(v - __half2float(h));
        *reinterpret_cast<__half*>(smem + t * OV_PITCH + sidx * 2) = h;
        *reinterpret_cast<__half*>(smem + O_AMAT + t * OV_PITCH + sidx * 2) = l;
    }

    #pragma unroll
    for (int vc = 0; vc < 2; ++vc) {
        const int v0 = vt * 256 + vc * 128;
        const uint32_t sX = sb + O_XBASE + vc * O_XMAT;
        #pragma unroll
        for (int i = 0; i < 8; ++i) {
            int g = tid + i * 256;
            int r = g >> 4, cc = g & 15;
            int srow = T0 - 64 + r;
            size_t grow = (size_t)(b * L_ + (srow < 0 ? 0 : srow)) * H_ + v0 + cc * 8;
            CP_ASYNC16(sX + r * OV_PITCH + cc * 16, g_Xh + grow);
        }
        CP_COMMIT();
    }

    const uint32_t aAddr = sb + (uint32_t)((wm*32 + (lane & 15)) * OV_PITCH + ((lane >> 4) & 1) * 16);
    const int gid = lane >> 2, tig = lane & 3;

    #pragma unroll
    for (int vc = 0; vc < 2; ++vc) {
        if (vc == 0) { CP_WAIT(1); } else { CP_WAIT(0); }
        __syncthreads();

        const uint32_t sX = sb + O_XBASE + vc * O_XMAT;
        const uint32_t bAddr = sX + (uint32_t)((lane & 15) * OV_PITCH + (wn*32) * 2);

        float acc[2][4][4];
        #pragma unroll
        for (int i = 0; i < 2; ++i)
            #pragma unroll
            for (int j = 0; j < 4; ++j)
                #pragma unroll
                for (int q = 0; q < 4; ++q) acc[i][j][q] = 0.f;

        #pragma unroll
        for (int ks = 0; ks < 8; ++ks) {
            uint32_t ah[2][4], al[2][4];
            #pragma unroll
            for (int mi = 0; mi < 2; ++mi) {
                asm volatile("ldmatrix.sync.aligned.m8n8.x4.shared.b16 {%0,%1,%2,%3}, [%4];"
                    : "=r"(ah[mi][0]), "=r"(ah[mi][1]), "=r"(ah[mi][2]), "=r"(ah[mi][3])
                    : "r"(aAddr + mi * (16*OV_PITCH) + ks * 32));
                asm volatile("ldmatrix.sync.aligned.m8n8.x4.shared.b16 {%0,%1,%2,%3}, [%4];"
                    : "=r"(al[mi][0]), "=r"(al[mi][1]), "=r"(al[mi][2]), "=r"(al[mi][3])
                    : "r"(aAddr + O_AMAT + mi * (16*OV_PITCH) + ks * 32));
            }
            uint32_t bh[4][2];
            #pragma unroll
            for (int nf = 0; nf < 4; ++nf) {
                asm volatile("ldmatrix.sync.aligned.m8n8.x2.trans.shared.b16 {%0,%1}, [%2];"
                    : "=r"(bh[nf][0]), "=r"(bh[nf][1])
                    : "r"(bAddr + ks * (16*OV_PITCH) + nf * 16));
            }
            #pragma unroll
            for (int mi = 0; mi < 2; ++mi)
                #pragma unroll
                for (int nf = 0; nf < 4; ++nf) {
                    asm volatile(
                        "mma.sync.aligned.m16n8k16.row.col.f32.f16.f16.f32 "
                        "{%0,%1,%2,%3}, {%4,%5,%6,%7}, {%8,%9}, {%0,%1,%2,%3};"
                        : "+f"(acc[mi][nf][0]), "+f"(acc[mi][nf][1]),
                          "+f"(acc[mi][nf][2]), "+f"(acc[mi][nf][3])
                        : "r"(ah[mi][0]), "r"(ah[mi][1]), "r"(ah[mi][2]), "r"(ah[mi][3]),
                          "r"(bh[nf][0]), "r"(bh[nf][1]));
                    asm volatile(
                        "mma.sync.aligned.m16n8k16.row.col.f32.f16.f16.f32 "
                        "{%0,%1,%2,%3}, {%4,%5,%6,%7}, {%8,%9}, {%0,%1,%2,%3};"
                        : "+f"(acc[mi][nf][0]), "+f"(acc[mi][nf][1]),
                          "+f"(acc[mi][nf][2]), "+f"(acc[mi][nf][3])
                        : "r"(al[mi][0]), "r"(al[mi][1]), "r"(al[mi][2]), "r"(al[mi][3]),
                          "r"(bh[nf][0]), "r"(bh[nf][1]));
                }
        }

        #pragma unroll
        for (int mi = 0; mi < 2; ++mi) {
            #pragma unroll
            for (int nf = 0; nf < 4; ++nf) {
                int row = T0 + wm*32 + mi*16 + gid;
                int col = vt*256 + vc*128 + wn*32 + nf*8 + tig*2;
                size_t i0 = (size_t)(b * L_ + row) * H_ + col;
                size_t i1 = i0 + 8 * H_;
                __half2 h0; h0.x = __float2half_rn(acc[mi][nf][0]); h0.y = __float2half_rn(acc[mi][nf][1]);
                __half2 h1; h1.x = __float2half_rn(acc[mi][nf][2]); h1.y = __float2half_rn(acc[mi][nf][3]);
                *reinterpret_cast<__half2*>(&g_O16[i0]) = h0;
                *reinterpret_cast<__half2*>(&g_O16[i1]) = h1;
            }
        }
    }
}

// ============ 3b) per-row rms factor from o16 ============
__global__ void rms_kernel() {
    const int m = blockIdx.x;
    const int tid = threadIdx.x;
    const __half* orow = &g_O16[(size_t)m * H_];
    float ss = 0.f;
    #pragma unroll
    for (int t = 0; t < 4; ++t) {
        __half2 h = *reinterpret_cast<const __half2*>(&orow[tid * 8 + t * 2]);
        float2 f = __half22float2(h);
        ss += f.x * f.x + f.y * f.y;
    }
    #pragma unroll
    for (int o = 16; o > 0; o >>= 1)
        ss += __shfl_xor_sync(0xffffffffu, ss, o);
    __shared__ float red[8];
    if ((tid & 31) == 0) red[tid >> 5] = ss;
    __syncthreads();
    if (tid == 0) {
        float t = 0.f;
        #pragma unroll
        for (int i = 0; i < 8; ++i) t += red[i];
        g_rs[m] = rsqrtf(t * (1.f / H_) + EPS_);
    }
}

// ============ 4) mma GEMM 128x128 tiles, 8 warps (64x32 each), occ 2 ============
#define G_ITERS  64
#define G_PITCH  144
#define G_ATILE  (128*G_PITCH)
#define G_STAGE  (256*G_PITCH)   // 36864
#define G_SMEM   (3*G_STAGE)     // 110592

__device__ __forceinline__ void g_load_stage(uint32_t sbase, int stage, int it,
                                             int m0, int n0, int tid) {
    const int kofs = it * 64;
    const __half* Ap = (kofs < H_) ? (g_O16 + kofs) : (g_Xh + (kofs - H_));
    const uint32_t sA = sbase + stage * G_STAGE;
    const uint32_t sB = sA + G_ATILE;
    #pragma unroll
    for (int i = 0; i < 4; ++i) {
        int g = tid + i * 256;
        int r = g >> 3, c = g & 7;
        CP_ASYNC16(sA + r * G_PITCH + c * 16,
                   Ap + (size_t)(m0 + r) * H_ + c * 8);
    }
    #pragma unroll
    for (int i = 0; i < 4; ++i) {
        int g = tid + i * 256;
        int r = g >> 3, c = g & 7;
        CP_ASYNC16(sB + r * G_PITCH + c * 16,
                   g_Bh + (size_t)(n0 + r) * (2*H_) + kofs + c * 8);
    }
}

__global__ void __launch_bounds__(256, 2) gemm_tc_kernel(const float* __restrict__ gw,
                                                         float* __restrict__ out) {
    extern __shared__ char smem[];
    const uint32_t sbase = smem_u32(smem);
    const int tid = threadIdx.x;
    const int lane = tid & 31;
    const int wid = tid >> 5;
    const int wm = wid & 1;          // 2 warps in m (64 rows each)
    const int wn = wid >> 1;         // 4 warps in n (32 cols each)
    const int m0 = blockIdx.y * 128;
    const int n0 = blockIdx.x * 128;

    const uint32_t aAddr = (uint32_t)((wm*64 + (lane & 15)) * G_PITCH + ((lane >> 4) & 1) * 16);
    const uint32_t bAddr = (uint32_t)(G_ATILE +
                    (wn*32 + (lane & 7) + ((lane & 16) ? 8 : 0)) * G_PITCH +
                    ((lane & 8) ? 16 : 0));

    float c[4][4][4];
    #pragma unroll
    for (int i = 0; i < 4; ++i)
        #pragma unroll
        for (int j = 0; j < 4; ++j)
            #pragma unroll
            for (int q = 0; q < 4; ++q) c[i][j][q] = 0.f;

    g_load_stage(sbase, 0, 0, m0, n0, tid); CP_COMMIT();
    g_load_stage(sbase, 1, 1, m0, n0, tid); CP_COMMIT();

    int stage = 0;
    #pragma unroll 1
    for (int it = 0; it < G_ITERS; ++it) {
        CP_WAIT(1);
        __syncthreads();
        if (it + 2 < G_ITERS) {
            int ns = stage + 2; if (ns >= 3) ns -= 3;
            g_load_stage(sbase, ns, it + 2, m0, n0, tid);
        }
        CP_COMMIT();

        const uint32_t stoff = sbase + stage * G_STAGE;
        #pragma unroll
        for (int ks = 0; ks < 4; ++ks) {
            uint32_t af[4][4];
            #pragma unroll
            for (int mi = 0; mi < 4; ++mi) {
                asm volatile("ldmatrix.sync.aligned.m8n8.x4.shared.b16 {%0,%1,%2,%3}, [%4];"
                    : "=r"(af[mi][0]), "=r"(af[mi][1]), "=r"(af[mi][2]), "=r"(af[mi][3])
                    : "r"(stoff + aAddr + mi * (16*G_PITCH) + ks * 32));
            }
            uint32_t bf[4][2];
            #pragma unroll
            for (int p = 0; p < 2; ++p) {
                asm volatile("ldmatrix.sync.aligned.m8n8.x4.shared.b16 {%0,%1,%2,%3}, [%4];"
                    : "=r"(bf[p*2][0]), "=r"(bf[p*2][1]), "=r"(bf[p*2+1][0]), "=r"(bf[p*2+1][1])
                    : "r"(stoff + bAddr + p * (16*G_PITCH) + ks * 32));
            }
            #pragma unroll
            for (int mi = 0; mi < 4; ++mi)
                #pragma unroll
                for (int ni = 0; ni < 4; ++ni) {
                    asm volatile(
                        "mma.sync.aligned.m16n8k16.row.col.f32.f16.f16.f32 "
                        "{%0,%1,%2,%3}, {%4,%5,%6,%7}, {%8,%9}, {%0,%1,%2,%3};"
                        : "+f"(c[mi][ni][0]), "+f"(c[mi][ni][1]),
                          "+f"(c[mi][ni][2]), "+f"(c[mi][ni][3])
                        : "r"(af[mi][0]), "r"(af[mi][1]), "r"(af[mi][2]), "r"(af[mi][3]),
                          "r"(bf[ni][0]), "r"(bf[ni][1]));
                }
        }
        if (++stage == 3) stage = 0;
    }

    // fused epilogue: out = o*rs*gw * go * sigmoid(go)
    const int gid = lane >> 2, tig = lane & 3;
    #pragma unroll
    for (int mi = 0; mi < 4; ++mi) {
        int row = m0 + wm*64 + mi*16 + gid;
        float rs0 = g_rs[row];
        float rs1 = g_rs[row + 8];
        #pragma unroll
        for (int ni = 0; ni < 4; ++ni) {
            int col = n0 + wn*32 + ni*8 + tig*2;
            float2 gwv = *reinterpret_cast<const float2*>(&gw[col]);
            size_t i0 = (size_t)row * H_ + col;
            size_t i1 = i0 + 8 * H_;
            float2 o0 = __half22float2(*reinterpret_cast<const __half2*>(&g_O16[i0]));
            float2 o1 = __half22float2(*reinterpret_cast<const __half2*>(&g_O16[i1]));
            float go;
            float2 r0, r1;
            go = c[mi][ni][0]; r0.x = o0.x * rs0 * gwv.x * go * sigmoid_f(go);
            go = c[mi][ni][1]; r0.y = o0.y * rs0 * gwv.y * go * sigmoid_f(go);
            go = c[mi][ni][2]; r1.x = o1.x * rs1 * gwv.x * go * sigmoid_f(go);
            go = c[mi][ni][3]; r1.y = o1.y * rs1 * gwv.y * go * sigmoid_f(go);
            *reinterpret_cast<float2*>(&out[i0]) = r0;
            *reinterpret_cast<float2*>(&out[i1]) = r1;
        }
    }
}

// ---------------------------------------------------------------------
extern "C" void kernel_launch(void* const* d_in, const int* in_sizes, int n_in,
                              void* d_out, int out_size) {
    const float* x   = (const float*)d_in[0];
    const float* Wq  = (const float*)d_in[1];
    const float* Wk  = (const float*)d_in[2];
    const float* Wog = (const float*)d_in[3];
    const float* Wig = (const float*)d_in[4];
    const float* gw  = (const float*)d_in[5];
    float* out = (float*)d_out;

    cudaFuncSetAttribute(proj_tc_kernel, cudaFuncAttributeMaxDynamicSharedMemorySize, P_SMEM);
    cudaFuncSetAttribute(gla_o_tc_kernel, cudaFuncAttributeMaxDynamicSharedMemorySize, O_SMEM);
    cudaFuncSetAttribute(gemm_tc_kernel, cudaFuncAttributeMaxDynamicSharedMemorySize, G_SMEM);

    conv_all_kernel<<<NBLK_X + NBLK_W + NBLK_B, 256>>>(x, Wq, Wk, Wog, Wig);
    proj_tc_kernel<<<dim3(4, 32),    128, P_SMEM>>>();
    gla_A_kernel <<<dim3(NT_, B_, 4), 512>>>();
    gla_o_tc_kernel<<<dim3(H_/256, NT_, B_), 256, O_SMEM>>>();
    rms_kernel   <<<BL_,             256>>>();
    gemm_tc_kernel<<<dim3(H_/128, BL_/128), 256, G_SMEM>>>(gw, out);
}